// round 1
// baseline (speedup 1.0000x reference)
#include <cuda_runtime.h>
#include <cuda_bf16.h>
#include <math.h>

// ---------------- problem constants ----------------
#define BATCH   256
#define RANK    16
#define IN_D    784
#define H1      512
#define OUT_D   10
#define KDIM    128      // g1 feature dim
#define TOTAL   29610    // generated params per sample

// g layout offsets (per sample, row-major slice order from reference)
#define O_A1    0               // [512][16]
#define O_B1    8192            // [16][784]
#define O_BIAS1 20736           // [512]
#define O_A2    21248           // [10][16]
#define O_B2    21408           // [16][512]
#define O_BIAS2 29600           // [10]

// ---------------- scratch (__device__ globals; no allocs allowed) ----------
__device__ float s_conv1[BATCH * 16 * 14 * 14];   // 3.2 MB
__device__ float s_conv2[BATCH * 32 * 7 * 7];     // 1.6 MB  (== h flat, 1568/sample)
__device__ float s_style[BATCH * 64];
__device__ float s_g1   [BATCH * KDIM];
__device__ float s_g    [(size_t)BATCH * TOTAL];  // 30.3 MB

// ---------------- conv1: 1->16 ch, 3x3 s2 p1, relu ----------------
__global__ void conv1_k(const float* __restrict__ img,
                        const float* __restrict__ w,
                        const float* __restrict__ bias) {
    int idx = blockIdx.x * blockDim.x + threadIdx.x;
    if (idx >= BATCH * 16 * 14 * 14) return;
    int x = idx % 14;
    int t = idx / 14;
    int y = t % 14; t /= 14;
    int c = t % 16;
    int b = t / 16;
    float acc = bias[c];
    const float* ip = img + b * 784;
    const float* wp = w + c * 9;
    int iy0 = y * 2 - 1, ix0 = x * 2 - 1;
#pragma unroll
    for (int ky = 0; ky < 3; ky++) {
        int iy = iy0 + ky;
        if (iy < 0 || iy >= 28) continue;
#pragma unroll
        for (int kx = 0; kx < 3; kx++) {
            int ix = ix0 + kx;
            if (ix < 0 || ix >= 28) continue;
            acc += ip[iy * 28 + ix] * wp[ky * 3 + kx];
        }
    }
    s_conv1[idx] = fmaxf(acc, 0.f);
}

// ---------------- conv2: 16->32 ch, 3x3 s2 p1, relu ----------------
__global__ void conv2_k(const float* __restrict__ w,
                        const float* __restrict__ bias) {
    int oc = blockIdx.x;       // 32
    int b  = blockIdx.y;       // 256
    __shared__ float ws[144];
    for (int i = threadIdx.x; i < 144; i += 64) ws[i] = w[oc * 144 + i];
    __syncthreads();
    int t = threadIdx.x;
    if (t >= 49) return;
    int y = t / 7, x = t % 7;
    float acc = bias[oc];
    const float* ip = s_conv1 + b * 16 * 196;
    int iy0 = y * 2 - 1, ix0 = x * 2 - 1;
#pragma unroll
    for (int ic = 0; ic < 16; ic++) {
        const float* p  = ip + ic * 196;
        const float* wp = ws + ic * 9;
#pragma unroll
        for (int ky = 0; ky < 3; ky++) {
            int iy = iy0 + ky;
            if (iy < 0 || iy >= 14) continue;
#pragma unroll
            for (int kx = 0; kx < 3; kx++) {
                int ix = ix0 + kx;
                if (ix < 0 || ix >= 14) continue;
                acc += p[iy * 14 + ix] * wp[ky * 3 + kx];
            }
        }
    }
    s_conv2[(b * 32 + oc) * 49 + y * 7 + x] = fmaxf(acc, 0.f);
}

// ---------------- style = tanh(h @ sew.T + seb), one warp per (b,j) --------
__global__ void style_k(const float* __restrict__ sew,
                        const float* __restrict__ seb) {
    int warp = threadIdx.x >> 5, lane = threadIdx.x & 31;
    int pair = blockIdx.x * 8 + warp;          // 256*64 pairs
    int b = pair >> 6, j = pair & 63;
    const float* hp = s_conv2 + b * 1568;
    const float* wp = sew + j * 1568;
    float acc = 0.f;
    for (int i = lane; i < 1568; i += 32) acc += hp[i] * wp[i];
#pragma unroll
    for (int o = 16; o > 0; o >>= 1) acc += __shfl_xor_sync(0xffffffffu, acc, o);
    if (lane == 0) s_style[b * 64 + j] = tanhf(acc + seb[j]);
}

// ---------------- g1 = relu(style @ g1w.T + g1b), block per sample ---------
__global__ void g1_k(const float* __restrict__ g1w,
                     const float* __restrict__ g1b) {
    int b = blockIdx.x;
    int o = threadIdx.x;   // 128
    __shared__ float st[64];
    if (o < 64) st[o] = s_style[b * 64 + o];
    __syncthreads();
    float acc = g1b[o];
    const float* wp = g1w + o * 64;
#pragma unroll
    for (int k = 0; k < 64; k++) acc += st[k] * wp[k];
    s_g1[b * KDIM + o] = fmaxf(acc, 0.f);
}

// ---------------- generator GEMM: g[s][m] = g1[s] . g2w[m] + g2b[m] --------
// M = TOTAL(29610) rows of g2w, N = 256 samples, K = 128.
// BM=64, BN=64, BK=16, 256 threads, 4x4 register tile per thread.
__global__ void gemm_k(const float* __restrict__ g2w,
                       const float* __restrict__ g2b) {
    __shared__ float As[16][64];   // [k][m]
    __shared__ float Bs[16][64];   // [k][n]
    int bm = blockIdx.x * 64;
    int bn = blockIdx.y * 64;
    int tid = threadIdx.x;
    int tx = tid & 15;             // M direction
    int ty = tid >> 4;             // N direction
    float acc[4][4] = {};          // [n][m]

    int lm = tid >> 2;             // row/sample within tile for loading
    int kq = (tid & 3) * 4;        // k quad

    for (int k0 = 0; k0 < KDIM; k0 += 16) {
        {
            int row = bm + lm;
            float4 v = (row < TOTAL)
                ? *(const float4*)(g2w + (size_t)row * KDIM + k0 + kq)
                : make_float4(0.f, 0.f, 0.f, 0.f);
            As[kq + 0][lm] = v.x; As[kq + 1][lm] = v.y;
            As[kq + 2][lm] = v.z; As[kq + 3][lm] = v.w;
        }
        {
            float4 v = *(const float4*)(s_g1 + (size_t)(bn + lm) * KDIM + k0 + kq);
            Bs[kq + 0][lm] = v.x; Bs[kq + 1][lm] = v.y;
            Bs[kq + 2][lm] = v.z; Bs[kq + 3][lm] = v.w;
        }
        __syncthreads();
#pragma unroll
        for (int k = 0; k < 16; k++) {
            float4 a4 = *(const float4*)&As[k][tx * 4];
            float4 b4 = *(const float4*)&Bs[k][ty * 4];
            float a[4] = {a4.x, a4.y, a4.z, a4.w};
            float bb[4] = {b4.x, b4.y, b4.z, b4.w};
#pragma unroll
            for (int j = 0; j < 4; j++)
#pragma unroll
                for (int i = 0; i < 4; i++)
                    acc[j][i] += bb[j] * a[i];
        }
        __syncthreads();
    }

#pragma unroll
    for (int j = 0; j < 4; j++) {
        int s = bn + ty * 4 + j;
        float* gp = s_g + (size_t)s * TOTAL;
#pragma unroll
        for (int i = 0; i < 4; i++) {
            int m = bm + tx * 4 + i;
            if (m < TOTAL) gp[m] = acc[j][i] + g2b[m];
        }
    }
}

// ---------------- apply: per-sample low-rank MLP -----------------
// h1 = relu(a1 @ (b1f @ x) + bias1); out = a2 @ (b2f @ h1) + bias2
__global__ void apply_k(const float* __restrict__ img,
                        float* __restrict__ out) {
    int b = blockIdx.x;
    __shared__ float xs[IN_D];
    __shared__ float h1[H1];
    __shared__ float t1[RANK];
    __shared__ float t2[RANK];
    int tid = threadIdx.x;            // 512
    int warp = tid >> 5, lane = tid & 31;
    const float* gb = s_g + (size_t)b * TOTAL;
    const float* xp = img + b * IN_D;

    for (int i = tid; i < IN_D; i += 512) xs[i] = xp[i];
    __syncthreads();

    // t1[r] = b1f[r] . x   (16 warps, one r each)
    {
        const float* bp = gb + O_B1 + warp * IN_D;
        float acc = 0.f;
        for (int i = lane; i < IN_D; i += 32) acc += bp[i] * xs[i];
#pragma unroll
        for (int o = 16; o > 0; o >>= 1) acc += __shfl_xor_sync(0xffffffffu, acc, o);
        if (lane == 0) t1[warp] = acc;
    }
    __syncthreads();

    // h1[o] = relu(a1[o] . t1 + bias1[o])
    {
        const float* ap = gb + O_A1 + tid * RANK;
        float acc = gb[O_BIAS1 + tid];
#pragma unroll
        for (int r = 0; r < RANK; r++) acc += ap[r] * t1[r];
        h1[tid] = fmaxf(acc, 0.f);
    }
    __syncthreads();

    // t2[r] = b2f[r] . h1
    {
        const float* bp = gb + O_B2 + warp * H1;
        float acc = 0.f;
        for (int i = lane; i < H1; i += 32) acc += bp[i] * h1[i];
#pragma unroll
        for (int o = 16; o > 0; o >>= 1) acc += __shfl_xor_sync(0xffffffffu, acc, o);
        if (lane == 0) t2[warp] = acc;
    }
    __syncthreads();

    // out[o] = a2[o] . t2 + bias2[o]
    if (tid < OUT_D) {
        const float* ap = gb + O_A2 + tid * RANK;
        float acc = gb[O_BIAS2 + tid];
#pragma unroll
        for (int r = 0; r < RANK; r++) acc += ap[r] * t2[r];
        out[b * OUT_D + tid] = acc;
    }
}

// ---------------- launch ----------------
extern "C" void kernel_launch(void* const* d_in, const int* in_sizes, int n_in,
                              void* d_out, int out_size) {
    const float* images = (const float*)d_in[0];
    const float* c1w    = (const float*)d_in[1];
    const float* c1b    = (const float*)d_in[2];
    const float* c2w    = (const float*)d_in[3];
    const float* c2b    = (const float*)d_in[4];
    const float* sew    = (const float*)d_in[5];
    const float* seb    = (const float*)d_in[6];
    const float* g1w    = (const float*)d_in[7];
    const float* g1b    = (const float*)d_in[8];
    const float* g2w    = (const float*)d_in[9];
    const float* g2b    = (const float*)d_in[10];
    float* out = (float*)d_out;

    conv1_k<<<(BATCH * 16 * 14 * 14 + 255) / 256, 256>>>(images, c1w, c1b);
    conv2_k<<<dim3(32, BATCH), 64>>>(c2w, c2b);
    style_k<<<(BATCH * 64) / 8, 256>>>(sew, seb);
    g1_k<<<BATCH, 128>>>(g1w, g1b);
    gemm_k<<<dim3((TOTAL + 63) / 64, BATCH / 64), 256>>>(g2w, g2b);
    apply_k<<<BATCH, 512>>>(images, out);
}